// round 15
// baseline (speedup 1.0000x reference)
#include <cuda_runtime.h>

#define N_NODES 50000
#define N_EDGES 800000
#define IN_CH 128
#define HID 64

#define SB 512
#define NSB ((N_NODES + SB - 1) / SB)   // 98

// ---------------- scratch (static device globals: allocation-free) ----------
__device__ int   g_deg[N_NODES];
__device__ int   g_off[N_NODES];    // block-local exclusive prefix (scan1)
__device__ int   g_woff[N_NODES];   // same, consumed by fill's atomicAdd
__device__ int   g_part[NSB];       // exclusive block prefixes (scan2)
__device__ int   g_csr[N_EDGES];
__device__ float g_y2[N_NODES * 128];   // [N][128]: cols 0:64 = A@Wl, 64:128 = A@Wr
__device__ float g_h[N_NODES * 64];

// ---------------- f32x2 helpers ---------------------------------------------
__device__ __forceinline__ void fma2(unsigned long long& d,
                                     unsigned long long a,
                                     unsigned long long b) {
    asm("fma.rn.f32x2 %0, %1, %2, %0;" : "+l"(d) : "l"(a), "l"(b));
}
__device__ __forceinline__ float2 u2f(unsigned long long v) {
    float2 r;
    asm("mov.b64 {%0, %1}, %2;" : "=f"(r.x), "=f"(r.y) : "l"(v));
    return r;
}

// ---------------- CSR build (R14-validated) ----------------------------------
__global__ void zero_deg_kernel() {
    int i = blockIdx.x * blockDim.x + threadIdx.x;
    if (i < N_NODES) g_deg[i] = 0;
}

__global__ void hist_kernel(const int* __restrict__ dst) {
    int e = blockIdx.x * blockDim.x + threadIdx.x;
    if (e < N_EDGES) atomicAdd(&g_deg[dst[e]], 1);
}

__global__ void scan1_kernel() {   // per-block exclusive scan -> g_off, g_woff
    __shared__ int s[SB];
    int t = threadIdx.x;
    int i = blockIdx.x * SB + t;
    int v = (i < N_NODES) ? g_deg[i] : 0;
    s[t] = v;
    __syncthreads();
    #pragma unroll
    for (int d = 1; d < SB; d <<= 1) {
        int add = (t >= d) ? s[t - d] : 0;
        __syncthreads();
        s[t] += add;
        __syncthreads();
    }
    if (i < N_NODES) {
        int ex = s[t] - v;
        g_off[i] = ex;
        g_woff[i] = ex;
    }
    if (t == SB - 1) g_part[blockIdx.x] = s[t];
}

__global__ void scan2_kernel() {   // 1 block: exclusive scan of block totals
    __shared__ int s[128];
    int t = threadIdx.x;
    int v = (t < NSB) ? g_part[t] : 0;
    s[t] = v;
    __syncthreads();
    #pragma unroll
    for (int d = 1; d < 128; d <<= 1) {
        int add = (t >= d) ? s[t - d] : 0;
        __syncthreads();
        s[t] += add;
        __syncthreads();
    }
    if (t < NSB) g_part[t] = s[t] - v;
}

__global__ void fill_kernel(const int* __restrict__ src,
                            const int* __restrict__ dst) {
    int e = blockIdx.x * blockDim.x + threadIdx.x;
    if (e < N_EDGES) {
        int d = dst[e];
        int pos = atomicAdd(&g_woff[d], 1) + g_part[d >> 9];
        g_csr[pos] = src[e];
    }
}

// ---------------- merged GEMM (R13/R14-validated, + PDL hooks) ---------------
template<int K, int ASEL>
__global__ void __launch_bounds__(256) gemm2_kernel(const float* __restrict__ Aext,
                                                    const float* __restrict__ Wl,
                                                    const float* __restrict__ Wr) {
    const float* A = (ASEL == 1) ? (const float*)g_h : Aext;

    __shared__ float Ws[32][128];
    __shared__ float Asd[16][136];

    int tid = threadIdx.x;
    int tx = tid & 15;
    int ty = tid >> 4;
    int rbase = blockIdx.x * 64;

    unsigned long long acc[4][4] = {};
    int ar = tid >> 2;
    int ak4 = (tid & 3) << 2;

    if (ASEL == 1) cudaGridDependencySynchronize();

    for (int kc = 0; kc < K; kc += 32) {
        for (int ks = 0; ks < 32; ks += 16) {
            if (ks == 0) {
                #pragma unroll
                for (int i = 0; i < 4; i++) {
                    int li = tid + i * 256;
                    int wk = li >> 5;
                    int wc4 = (li & 31) << 2;
                    const float* srcp = (wc4 < 64)
                        ? (Wl + (size_t)(kc + wk) * 64 + wc4)
                        : (Wr + (size_t)(kc + wk) * 64 + (wc4 - 64));
                    *(float4*)&Ws[wk][wc4] = *(const float4*)srcp;
                }
            }
            {
                int gr = rbase + ar;
                float4 a = make_float4(0.f, 0.f, 0.f, 0.f);
                if (gr < N_NODES)
                    a = *(const float4*)(A + (size_t)gr * K + kc + ks + ak4);
                *(float2*)&Asd[ak4 + 0][2 * ar] = make_float2(a.x, a.x);
                *(float2*)&Asd[ak4 + 1][2 * ar] = make_float2(a.y, a.y);
                *(float2*)&Asd[ak4 + 2][2 * ar] = make_float2(a.z, a.z);
                *(float2*)&Asd[ak4 + 3][2 * ar] = make_float2(a.w, a.w);
            }
            __syncthreads();

            #pragma unroll
            for (int k = 0; k < 16; k++) {
                ulonglong2 a01 = *(const ulonglong2*)&Asd[k][ty * 8];
                ulonglong2 a23 = *(const ulonglong2*)&Asd[k][ty * 8 + 4];
                ulonglong2 w01 = *(const ulonglong2*)&Ws[ks + k][tx * 4];
                ulonglong2 w23 = *(const ulonglong2*)&Ws[ks + k][64 + tx * 4];
                fma2(acc[0][0], a01.x, w01.x); fma2(acc[0][1], a01.x, w01.y);
                fma2(acc[0][2], a01.x, w23.x); fma2(acc[0][3], a01.x, w23.y);
                fma2(acc[1][0], a01.y, w01.x); fma2(acc[1][1], a01.y, w01.y);
                fma2(acc[1][2], a01.y, w23.x); fma2(acc[1][3], a01.y, w23.y);
                fma2(acc[2][0], a23.x, w01.x); fma2(acc[2][1], a23.x, w01.y);
                fma2(acc[2][2], a23.x, w23.x); fma2(acc[2][3], a23.x, w23.y);
                fma2(acc[3][0], a23.y, w01.x); fma2(acc[3][1], a23.y, w01.y);
                fma2(acc[3][2], a23.y, w23.x); fma2(acc[3][3], a23.y, w23.y);
            }
            __syncthreads();
        }
    }

    cudaTriggerProgrammaticLaunchCompletion();

    #pragma unroll
    for (int i = 0; i < 4; i++) {
        int r = rbase + ty * 4 + i;
        if (r >= N_NODES) continue;
        float2 p0 = u2f(acc[i][0]);
        float2 p1 = u2f(acc[i][1]);
        float2 p2 = u2f(acc[i][2]);
        float2 p3 = u2f(acc[i][3]);
        *(float4*)(g_y2 + (size_t)r * 128 + tx * 4) =
            make_float4(p0.x, p0.y, p1.x, p1.y);
        *(float4*)(g_y2 + (size_t)r * 128 + 64 + tx * 4) =
            make_float4(p2.x, p2.y, p3.x, p3.y);
    }
}

// ---------------- gather + combine ------------------------------------------
// One warp per node, half-warp per edge, float4 lanes (R14 layout), but the
// 32-edge batch body is now a FULLY UNROLLED predicated loop: all 16 LDG.128
// per half-warp issue independently (MLP ~16) instead of a serial dynamic loop.
__global__ void __launch_bounds__(256) gather_kernel(const float* __restrict__ bias,
                                                     float* __restrict__ outp) {
    int gw = (blockIdx.x * blockDim.x + threadIdx.x) >> 5;
    int lane = threadIdx.x & 31;
    if (gw >= N_NODES) {
        cudaGridDependencySynchronize();
        return;
    }

    int off = g_off[gw] + g_part[gw >> 9];
    int deg = g_deg[gw];
    int half = lane >> 4;
    int c4 = (lane & 15) << 2;
    const unsigned FULL = 0xffffffffu;

    cudaGridDependencySynchronize();   // g_y2 from PDL primary

    float4 acc0 = make_float4(0.f, 0.f, 0.f, 0.f);
    float4 acc1 = make_float4(0.f, 0.f, 0.f, 0.f);

    for (int base = 0; base < deg; base += 32) {
        int n = min(32, deg - base);
        int sv = (lane < n) ? __ldg(&g_csr[off + base + lane]) : 0;

        // fully unrolled: e = 2k + half, k = 0..15; predicated independent loads
        #pragma unroll
        for (int k = 0; k < 16; k++) {
            int e = 2 * k + half;
            int s = __shfl_sync(FULL, sv, e);
            if (e < n) {
                float4 v = *(const float4*)(g_y2 + (size_t)s * 128 + c4);
                if (k & 1) {
                    acc1.x += v.x; acc1.y += v.y; acc1.z += v.z; acc1.w += v.w;
                } else {
                    acc0.x += v.x; acc0.y += v.y; acc0.z += v.z; acc0.w += v.w;
                }
            }
        }
    }

    cudaTriggerProgrammaticLaunchCompletion();

    float4 acc;
    acc.x = acc0.x + acc1.x;
    acc.y = acc0.y + acc1.y;
    acc.z = acc0.z + acc1.z;
    acc.w = acc0.w + acc1.w;
    acc.x += __shfl_down_sync(FULL, acc.x, 16);
    acc.y += __shfl_down_sync(FULL, acc.y, 16);
    acc.z += __shfl_down_sync(FULL, acc.z, 16);
    acc.w += __shfl_down_sync(FULL, acc.w, 16);

    if (half == 0) {
        float scale = 1.f / fmaxf((float)deg, 1.f);
        float4 z = *(const float4*)(g_y2 + (size_t)gw * 128 + 64 + c4);
        float4 b = *(const float4*)(bias + c4);
        float4 o;
        o.x = fmaxf(fmaf(acc.x, scale, z.x) + b.x, 0.f);
        o.y = fmaxf(fmaf(acc.y, scale, z.y) + b.y, 0.f);
        o.z = fmaxf(fmaf(acc.z, scale, z.z) + b.z, 0.f);
        o.w = fmaxf(fmaf(acc.w, scale, z.w) + b.w, 0.f);
        *(float4*)(outp + (size_t)gw * 64 + c4) = o;
    }
}

// ---------------- launch (R14-validated structure) ---------------------------
extern "C" void kernel_launch(void* const* d_in, const int* in_sizes, int n_in,
                              void* d_out, int out_size) {
    const float* x   = (const float*)d_in[0];
    const int*   ei  = (const int*)d_in[1];
    const float* w1l = (const float*)d_in[2];
    const float* w1r = (const float*)d_in[3];
    const float* b1  = (const float*)d_in[4];
    const float* w2l = (const float*)d_in[5];
    const float* w2r = (const float*)d_in[6];
    const float* b2  = (const float*)d_in[7];
    const int* src = ei;             // edge_index[0, :]
    const int* dst = ei + N_EDGES;   // edge_index[1, :]
    float* out = (float*)d_out;

    static cudaStream_t s2 = nullptr;
    static cudaEvent_t e_fork = nullptr, e_join = nullptr;
    static float* h_ptr = nullptr;
    if (!s2) {
        cudaStreamCreateWithFlags(&s2, cudaStreamNonBlocking);
        cudaEventCreateWithFlags(&e_fork, cudaEventDisableTiming);
        cudaEventCreateWithFlags(&e_join, cudaEventDisableTiming);
        cudaGetSymbolAddress((void**)&h_ptr, g_h);
    }

    const int gemm_grid   = (N_NODES + 63) / 64;            // 782
    const int gather_grid = (N_NODES * 32 + 255) / 256;     // 6250
    const int edge_grid   = (N_EDGES + 255) / 256;

    // ---- fork: CSR build on s2, concurrent with gemm1 on main stream ----
    cudaEventRecord(e_fork, 0);
    cudaStreamWaitEvent(s2, e_fork, 0);

    zero_deg_kernel<<<NSB, SB, 0, s2>>>();
    hist_kernel<<<edge_grid, 256, 0, s2>>>(dst);
    scan1_kernel<<<NSB, SB, 0, s2>>>();
    scan2_kernel<<<1, 128, 0, s2>>>();
    fill_kernel<<<edge_grid, 256, 0, s2>>>(src, dst);
    cudaEventRecord(e_join, s2);

    // PDL launch config for the three dependent main-stream kernels
    cudaLaunchAttribute pdl_attr[1];
    pdl_attr[0].id = cudaLaunchAttributeProgrammaticStreamSerialization;
    pdl_attr[0].val.programmaticStreamSerializationAllowed = 1;

    cudaLaunchConfig_t cfg_gather = {};
    cfg_gather.gridDim = dim3(gather_grid);
    cfg_gather.blockDim = dim3(256);
    cfg_gather.stream = 0;
    cfg_gather.attrs = pdl_attr;
    cfg_gather.numAttrs = 1;

    cudaLaunchConfig_t cfg_gemm = cfg_gather;
    cfg_gemm.gridDim = dim3(gemm_grid);

    // main stream: layer-1 GEMM concurrent with CSR build (no PDL: first kernel)
    gemm2_kernel<IN_CH, 0><<<gemm_grid, 256>>>(x, w1l, w1r);   // g_y2 = x@[w1l|w1r]

    // ---- join: gather needs both CSR and g_y2 ----
    cudaStreamWaitEvent(0, e_join, 0);
    cudaLaunchKernelEx(&cfg_gather, gather_kernel, b1, (float*)h_ptr);   // g_h

    // ---- layer 2 ----
    cudaLaunchKernelEx(&cfg_gemm, gemm2_kernel<HID, 1>,
                       (const float*)nullptr, w2l, w2r);                 // g_y2 = h@[w2l|w2r]
    cudaLaunchKernelEx(&cfg_gather, gather_kernel, b2, out);             // out
}

// round 16
// speedup vs baseline: 1.0220x; 1.0220x over previous
#include <cuda_runtime.h>

#define N_NODES 50000
#define N_EDGES 800000
#define IN_CH 128
#define HID 64

#define SB 512
#define NSB ((N_NODES + SB - 1) / SB)   // 98

// ---------------- scratch (static device globals: allocation-free) ----------
__device__ int   g_deg[N_NODES];
__device__ int   g_off[N_NODES];    // block-local exclusive prefix (scan1)
__device__ int   g_woff[N_NODES];   // same, consumed by fill's atomicAdd
__device__ int   g_part[NSB];       // exclusive block prefixes (scan2)
__device__ int   g_csr[N_EDGES];
__device__ float g_y2[N_NODES * 128];   // [N][128]: cols 0:64 = A@Wl, 64:128 = A@Wr
__device__ float g_h[N_NODES * 64];

// ---------------- f32x2 helpers ---------------------------------------------
__device__ __forceinline__ void fma2(unsigned long long& d,
                                     unsigned long long a,
                                     unsigned long long b) {
    asm("fma.rn.f32x2 %0, %1, %2, %0;" : "+l"(d) : "l"(a), "l"(b));
}
__device__ __forceinline__ float2 u2f(unsigned long long v) {
    float2 r;
    asm("mov.b64 {%0, %1}, %2;" : "=f"(r.x), "=f"(r.y) : "l"(v));
    return r;
}

// ---------------- CSR build (R14-validated) ----------------------------------
__global__ void zero_deg_kernel() {
    int i = blockIdx.x * blockDim.x + threadIdx.x;
    if (i < N_NODES) g_deg[i] = 0;
}

__global__ void hist_kernel(const int* __restrict__ dst) {
    int e = blockIdx.x * blockDim.x + threadIdx.x;
    if (e < N_EDGES) atomicAdd(&g_deg[dst[e]], 1);
}

__global__ void scan1_kernel() {   // per-block exclusive scan -> g_off, g_woff
    __shared__ int s[SB];
    int t = threadIdx.x;
    int i = blockIdx.x * SB + t;
    int v = (i < N_NODES) ? g_deg[i] : 0;
    s[t] = v;
    __syncthreads();
    #pragma unroll
    for (int d = 1; d < SB; d <<= 1) {
        int add = (t >= d) ? s[t - d] : 0;
        __syncthreads();
        s[t] += add;
        __syncthreads();
    }
    if (i < N_NODES) {
        int ex = s[t] - v;
        g_off[i] = ex;
        g_woff[i] = ex;
    }
    if (t == SB - 1) g_part[blockIdx.x] = s[t];
}

__global__ void scan2_kernel() {   // 1 block: exclusive scan of block totals
    __shared__ int s[128];
    int t = threadIdx.x;
    int v = (t < NSB) ? g_part[t] : 0;
    s[t] = v;
    __syncthreads();
    #pragma unroll
    for (int d = 1; d < 128; d <<= 1) {
        int add = (t >= d) ? s[t - d] : 0;
        __syncthreads();
        s[t] += add;
        __syncthreads();
    }
    if (t < NSB) g_part[t] = s[t] - v;
}

__global__ void fill_kernel(const int* __restrict__ src,
                            const int* __restrict__ dst) {
    int e = blockIdx.x * blockDim.x + threadIdx.x;
    if (e < N_EDGES) {
        int d = dst[e];
        int pos = atomicAdd(&g_woff[d], 1) + g_part[d >> 9];
        g_csr[pos] = src[e];
    }
}

// ---------------- merged GEMM (R13/R14-validated, + PDL hooks) ---------------
template<int K, int ASEL>
__global__ void __launch_bounds__(256) gemm2_kernel(const float* __restrict__ Aext,
                                                    const float* __restrict__ Wl,
                                                    const float* __restrict__ Wr) {
    const float* A = (ASEL == 1) ? (const float*)g_h : Aext;

    __shared__ float Ws[32][128];
    __shared__ float Asd[16][136];

    int tid = threadIdx.x;
    int tx = tid & 15;
    int ty = tid >> 4;
    int rbase = blockIdx.x * 64;

    unsigned long long acc[4][4] = {};
    int ar = tid >> 2;
    int ak4 = (tid & 3) << 2;

    if (ASEL == 1) cudaGridDependencySynchronize();

    for (int kc = 0; kc < K; kc += 32) {
        for (int ks = 0; ks < 32; ks += 16) {
            if (ks == 0) {
                #pragma unroll
                for (int i = 0; i < 4; i++) {
                    int li = tid + i * 256;
                    int wk = li >> 5;
                    int wc4 = (li & 31) << 2;
                    const float* srcp = (wc4 < 64)
                        ? (Wl + (size_t)(kc + wk) * 64 + wc4)
                        : (Wr + (size_t)(kc + wk) * 64 + (wc4 - 64));
                    *(float4*)&Ws[wk][wc4] = *(const float4*)srcp;
                }
            }
            {
                int gr = rbase + ar;
                float4 a = make_float4(0.f, 0.f, 0.f, 0.f);
                if (gr < N_NODES)
                    a = *(const float4*)(A + (size_t)gr * K + kc + ks + ak4);
                *(float2*)&Asd[ak4 + 0][2 * ar] = make_float2(a.x, a.x);
                *(float2*)&Asd[ak4 + 1][2 * ar] = make_float2(a.y, a.y);
                *(float2*)&Asd[ak4 + 2][2 * ar] = make_float2(a.z, a.z);
                *(float2*)&Asd[ak4 + 3][2 * ar] = make_float2(a.w, a.w);
            }
            __syncthreads();

            #pragma unroll
            for (int k = 0; k < 16; k++) {
                ulonglong2 a01 = *(const ulonglong2*)&Asd[k][ty * 8];
                ulonglong2 a23 = *(const ulonglong2*)&Asd[k][ty * 8 + 4];
                ulonglong2 w01 = *(const ulonglong2*)&Ws[ks + k][tx * 4];
                ulonglong2 w23 = *(const ulonglong2*)&Ws[ks + k][64 + tx * 4];
                fma2(acc[0][0], a01.x, w01.x); fma2(acc[0][1], a01.x, w01.y);
                fma2(acc[0][2], a01.x, w23.x); fma2(acc[0][3], a01.x, w23.y);
                fma2(acc[1][0], a01.y, w01.x); fma2(acc[1][1], a01.y, w01.y);
                fma2(acc[1][2], a01.y, w23.x); fma2(acc[1][3], a01.y, w23.y);
                fma2(acc[2][0], a23.x, w01.x); fma2(acc[2][1], a23.x, w01.y);
                fma2(acc[2][2], a23.x, w23.x); fma2(acc[2][3], a23.x, w23.y);
                fma2(acc[3][0], a23.y, w01.x); fma2(acc[3][1], a23.y, w01.y);
                fma2(acc[3][2], a23.y, w23.x); fma2(acc[3][3], a23.y, w23.y);
            }
            __syncthreads();
        }
    }

    cudaTriggerProgrammaticLaunchCompletion();

    #pragma unroll
    for (int i = 0; i < 4; i++) {
        int r = rbase + ty * 4 + i;
        if (r >= N_NODES) continue;
        float2 p0 = u2f(acc[i][0]);
        float2 p1 = u2f(acc[i][1]);
        float2 p2 = u2f(acc[i][2]);
        float2 p3 = u2f(acc[i][3]);
        *(float4*)(g_y2 + (size_t)r * 128 + tx * 4) =
            make_float4(p0.x, p0.y, p1.x, p1.y);
        *(float4*)(g_y2 + (size_t)r * 128 + 64 + tx * 4) =
            make_float4(p2.x, p2.y, p3.x, p3.y);
    }
}

// ---------------- gather + combine ------------------------------------------
// One warp per node, half-warp per edge, float4 lanes (R14 layout).
// Full groups of 8 edges (4 per half-warp): the 4 independent LDG.128 issue
// before any accumulate -> MLP 4. Remainder handled by the validated R14
// 2-edge / 1-edge tails. Instruction cost stays proportional to deg.
__global__ void __launch_bounds__(256) gather_kernel(const float* __restrict__ bias,
                                                     float* __restrict__ outp) {
    int gw = (blockIdx.x * blockDim.x + threadIdx.x) >> 5;
    int lane = threadIdx.x & 31;
    if (gw >= N_NODES) {
        cudaGridDependencySynchronize();
        return;
    }

    int off = g_off[gw] + g_part[gw >> 9];
    int deg = g_deg[gw];
    int half = lane >> 4;
    int c4 = (lane & 15) << 2;
    const unsigned FULL = 0xffffffffu;

    cudaGridDependencySynchronize();   // g_y2 from PDL primary

    float4 acc0 = make_float4(0.f, 0.f, 0.f, 0.f);
    float4 acc1 = make_float4(0.f, 0.f, 0.f, 0.f);

    for (int base = 0; base < deg; base += 32) {
        int n = min(32, deg - base);
        int sv = (lane < n) ? __ldg(&g_csr[off + base + lane]) : 0;
        int k = 0;
        // full groups of 8: 4 edges per half-warp, loads batched for MLP 4
        for (; k + 8 <= n; k += 8) {
            int s0 = __shfl_sync(FULL, sv, k + half);
            int s1 = __shfl_sync(FULL, sv, k + 2 + half);
            int s2 = __shfl_sync(FULL, sv, k + 4 + half);
            int s3 = __shfl_sync(FULL, sv, k + 6 + half);
            float4 v0 = *(const float4*)(g_y2 + (size_t)s0 * 128 + c4);
            float4 v1 = *(const float4*)(g_y2 + (size_t)s1 * 128 + c4);
            float4 v2 = *(const float4*)(g_y2 + (size_t)s2 * 128 + c4);
            float4 v3 = *(const float4*)(g_y2 + (size_t)s3 * 128 + c4);
            acc0.x += v0.x; acc0.y += v0.y; acc0.z += v0.z; acc0.w += v0.w;
            acc1.x += v1.x; acc1.y += v1.y; acc1.z += v1.z; acc1.w += v1.w;
            acc0.x += v2.x; acc0.y += v2.y; acc0.z += v2.z; acc0.w += v2.w;
            acc1.x += v3.x; acc1.y += v3.y; acc1.z += v3.z; acc1.w += v3.w;
        }
        // 2-edge steps (R14-validated)
        for (; k + 2 <= n; k += 2) {
            int sa = __shfl_sync(FULL, sv, k + half);
            float4 va = *(const float4*)(g_y2 + (size_t)sa * 128 + c4);
            acc0.x += va.x; acc0.y += va.y; acc0.z += va.z; acc0.w += va.w;
        }
        // final odd edge: lanes 0-15 only
        if (k < n) {
            int sa = __shfl_sync(FULL, sv, k);
            if (half == 0) {
                float4 va = *(const float4*)(g_y2 + (size_t)sa * 128 + c4);
                acc0.x += va.x; acc0.y += va.y; acc0.z += va.z; acc0.w += va.w;
            }
        }
    }

    cudaTriggerProgrammaticLaunchCompletion();

    float4 acc;
    acc.x = acc0.x + acc1.x;
    acc.y = acc0.y + acc1.y;
    acc.z = acc0.z + acc1.z;
    acc.w = acc0.w + acc1.w;
    acc.x += __shfl_down_sync(FULL, acc.x, 16);
    acc.y += __shfl_down_sync(FULL, acc.y, 16);
    acc.z += __shfl_down_sync(FULL, acc.z, 16);
    acc.w += __shfl_down_sync(FULL, acc.w, 16);

    if (half == 0) {
        float scale = 1.f / fmaxf((float)deg, 1.f);
        float4 z = *(const float4*)(g_y2 + (size_t)gw * 128 + 64 + c4);
        float4 b = *(const float4*)(bias + c4);
        float4 o;
        o.x = fmaxf(fmaf(acc.x, scale, z.x) + b.x, 0.f);
        o.y = fmaxf(fmaf(acc.y, scale, z.y) + b.y, 0.f);
        o.z = fmaxf(fmaf(acc.z, scale, z.z) + b.z, 0.f);
        o.w = fmaxf(fmaf(acc.w, scale, z.w) + b.w, 0.f);
        *(float4*)(outp + (size_t)gw * 64 + c4) = o;
    }
}

// ---------------- launch (R14-validated structure) ---------------------------
extern "C" void kernel_launch(void* const* d_in, const int* in_sizes, int n_in,
                              void* d_out, int out_size) {
    const float* x   = (const float*)d_in[0];
    const int*   ei  = (const int*)d_in[1];
    const float* w1l = (const float*)d_in[2];
    const float* w1r = (const float*)d_in[3];
    const float* b1  = (const float*)d_in[4];
    const float* w2l = (const float*)d_in[5];
    const float* w2r = (const float*)d_in[6];
    const float* b2  = (const float*)d_in[7];
    const int* src = ei;             // edge_index[0, :]
    const int* dst = ei + N_EDGES;   // edge_index[1, :]
    float* out = (float*)d_out;

    static cudaStream_t s2 = nullptr;
    static cudaEvent_t e_fork = nullptr, e_join = nullptr;
    static float* h_ptr = nullptr;
    if (!s2) {
        cudaStreamCreateWithFlags(&s2, cudaStreamNonBlocking);
        cudaEventCreateWithFlags(&e_fork, cudaEventDisableTiming);
        cudaEventCreateWithFlags(&e_join, cudaEventDisableTiming);
        cudaGetSymbolAddress((void**)&h_ptr, g_h);
    }

    const int gemm_grid   = (N_NODES + 63) / 64;            // 782
    const int gather_grid = (N_NODES * 32 + 255) / 256;     // 6250
    const int edge_grid   = (N_EDGES + 255) / 256;

    // ---- fork: CSR build on s2, concurrent with gemm1 on main stream ----
    cudaEventRecord(e_fork, 0);
    cudaStreamWaitEvent(s2, e_fork, 0);

    zero_deg_kernel<<<NSB, SB, 0, s2>>>();
    hist_kernel<<<edge_grid, 256, 0, s2>>>(dst);
    scan1_kernel<<<NSB, SB, 0, s2>>>();
    scan2_kernel<<<1, 128, 0, s2>>>();
    fill_kernel<<<edge_grid, 256, 0, s2>>>(src, dst);
    cudaEventRecord(e_join, s2);

    // PDL launch config for the three dependent main-stream kernels
    cudaLaunchAttribute pdl_attr[1];
    pdl_attr[0].id = cudaLaunchAttributeProgrammaticStreamSerialization;
    pdl_attr[0].val.programmaticStreamSerializationAllowed = 1;

    cudaLaunchConfig_t cfg_gather = {};
    cfg_gather.gridDim = dim3(gather_grid);
    cfg_gather.blockDim = dim3(256);
    cfg_gather.stream = 0;
    cfg_gather.attrs = pdl_attr;
    cfg_gather.numAttrs = 1;

    cudaLaunchConfig_t cfg_gemm = cfg_gather;
    cfg_gemm.gridDim = dim3(gemm_grid);

    // main stream: layer-1 GEMM concurrent with CSR build (no PDL: first kernel)
    gemm2_kernel<IN_CH, 0><<<gemm_grid, 256>>>(x, w1l, w1r);   // g_y2 = x@[w1l|w1r]

    // ---- join: gather needs both CSR and g_y2 ----
    cudaStreamWaitEvent(0, e_join, 0);
    cudaLaunchKernelEx(&cfg_gather, gather_kernel, b1, (float*)h_ptr);   // g_h

    // ---- layer 2 ----
    cudaLaunchKernelEx(&cfg_gemm, gemm2_kernel<HID, 1>,
                       (const float*)nullptr, w2l, w2r);                 // g_y2 = h@[w2l|w2r]
    cudaLaunchKernelEx(&cfg_gather, gather_kernel, b2, out);             // out
}